// round 2
// baseline (speedup 1.0000x reference)
#include <cuda_runtime.h>

// Problem constants
#define BB 2
#define SS 2048
#define DD 1024
#define HH 16
#define DKK 64
#define MM (BB*SS)      // 4096 rows
#define BHH (BB*HH)     // 32

// Scratch (device globals: allocation-free per harness rules)
__device__ float g_Q[BHH*SS*DKK];     // [b*H+h][s][dk]
__device__ float g_K[BHH*SS*DKK];
__device__ float g_V[BHH*SS*DKK];
__device__ float g_Ctx[MM*DD];        // [b,s, h*dk]  (attention output, head-concat layout)

// ---------------------------------------------------------------------------
// Kernel 1: per-head QKV projections.
// out[(b*H+h)][s][k] = sum_d X[b,s,d] * W[h,d,k]
// grid: (M/64, H, 3), block 256. 64x64 output tile, BK=16, 4x4 per thread.
// ---------------------------------------------------------------------------
__global__ __launch_bounds__(256) void proj_kernel(
    const float* __restrict__ q, const float* __restrict__ kin, const float* __restrict__ v,
    const float* __restrict__ Wq, const float* __restrict__ Wk, const float* __restrict__ Wv)
{
    __shared__ float As[16][65];   // As[kk][m]  (X tile, transposed on store)
    __shared__ float Bs[16][64];   // Bs[kk][n]  (W tile, natural)

    const int which = blockIdx.z;
    const float* X = (which == 0) ? q : (which == 1) ? kin : v;
    const float* W = (which == 0) ? Wq : (which == 1) ? Wk : Wv;
    float* Out = (which == 0) ? g_Q : (which == 1) ? g_K : g_V;

    const int h  = blockIdx.y;
    const int m0 = blockIdx.x * 64;
    const int tid = threadIdx.x;
    const int tx = tid & 15, ty = tid >> 4;
    const int lr = tid >> 2, lq = tid & 3;    // A load: row 0..63, k-quarter 0..3
    const int wr = tid >> 4, wq = tid & 15;   // B load: k-row 0..15, n-quarter 0..15

    float acc[4][4] = {};

    for (int k0 = 0; k0 < DD; k0 += 16) {
        float4 a4 = *reinterpret_cast<const float4*>(&X[(m0 + lr) * DD + k0 + lq * 4]);
        As[lq*4+0][lr] = a4.x; As[lq*4+1][lr] = a4.y;
        As[lq*4+2][lr] = a4.z; As[lq*4+3][lr] = a4.w;
        float4 b4 = *reinterpret_cast<const float4*>(&W[h * DD * DKK + (k0 + wr) * DKK + wq * 4]);
        *reinterpret_cast<float4*>(&Bs[wr][wq * 4]) = b4;
        __syncthreads();
        #pragma unroll
        for (int kk = 0; kk < 16; kk++) {
            float a[4], b[4];
            #pragma unroll
            for (int i = 0; i < 4; i++) a[i] = As[kk][ty * 4 + i];
            #pragma unroll
            for (int j = 0; j < 4; j++) b[j] = Bs[kk][tx * 4 + j];
            #pragma unroll
            for (int i = 0; i < 4; i++)
                #pragma unroll
                for (int j = 0; j < 4; j++)
                    acc[i][j] += a[i] * b[j];
        }
        __syncthreads();
    }

    #pragma unroll
    for (int i = 0; i < 4; i++) {
        int m = m0 + ty * 4 + i;
        int b_ = m / SS, s = m % SS;
        float* orow = &Out[((b_ * HH + h) * SS + s) * DKK];
        float4 o4 = make_float4(acc[i][0], acc[i][1], acc[i][2], acc[i][3]);
        *reinterpret_cast<float4*>(orow + tx * 4) = o4;
    }
}

// ---------------------------------------------------------------------------
// Kernel 2: causal flash attention. grid: (S/64, B*H), block 256.
// Per block: 64 query rows, stream 64-key tiles j=0..i with online softmax.
// Dynamic smem: Qs[64][65] (k-major), Ks[64][65] (k-major), Ps[64][65] (t-major), Vs[64][64]
// ---------------------------------------------------------------------------
__global__ __launch_bounds__(256) void attn_kernel()
{
    extern __shared__ float sm[];
    float (*Qs)[65] = (float(*)[65])(sm);                 // Qs[k][r]
    float (*Ks)[65] = (float(*)[65])(sm + 64 * 65);       // Ks[k][c]
    float (*Ps)[65] = (float(*)[65])(sm + 2 * 64 * 65);   // Ps[t][r]
    float (*Vs)[64] = (float(*)[64])(sm + 3 * 64 * 65);   // Vs[t][c]

    const int bh = blockIdx.y;
    const int qi = (gridDim.x - 1) - blockIdx.x;          // heavy tiles first
    const int i0 = qi * 64;
    const float* Qg = g_Q + (size_t)bh * SS * DKK;
    const float* Kg = g_K + (size_t)bh * SS * DKK;
    const float* Vg = g_V + (size_t)bh * SS * DKK;

    const int tid = threadIdx.x;
    const int tx = tid & 15, ty = tid >> 4;

    // load FULL 64x64 Q tile, transposed: Qs[k][r]   (4 float4 per thread)
    #pragma unroll
    for (int rep = 0; rep < 4; rep++) {
        int idx = tid + rep * 256;            // 0..1023 float4 slots
        int r = idx >> 4, c4 = idx & 15;      // row 0..63, k-quarter 0..15
        float4 a4 = *reinterpret_cast<const float4*>(&Qg[(i0 + r) * DKK + c4 * 4]);
        Qs[c4*4+0][r] = a4.x; Qs[c4*4+1][r] = a4.y;
        Qs[c4*4+2][r] = a4.z; Qs[c4*4+3][r] = a4.w;
    }

    float acc[4][4] = {};
    float mrow[4], lsum[4];
    #pragma unroll
    for (int i = 0; i < 4; i++) { mrow[i] = -1e30f; lsum[i] = 0.f; }
    const float scale = 0.125f;   // 1/sqrt(64)

    const int ntiles = qi + 1;
    for (int j = 0; j < ntiles; j++) {
        const int j0 = j * 64;
        __syncthreads();   // previous iteration's reads of Ks/Vs/Ps done
        // load FULL 64x64 K tile, transposed: Ks[k][c]
        #pragma unroll
        for (int rep = 0; rep < 4; rep++) {
            int idx = tid + rep * 256;
            int r = idx >> 4, c4 = idx & 15;
            float4 a4 = *reinterpret_cast<const float4*>(&Kg[(j0 + r) * DKK + c4 * 4]);
            Ks[c4*4+0][r] = a4.x; Ks[c4*4+1][r] = a4.y;
            Ks[c4*4+2][r] = a4.z; Ks[c4*4+3][r] = a4.w;
        }
        // load V tile natural [t][c]
        #pragma unroll
        for (int rep = 0; rep < 4; rep++) {
            int idx = tid + rep * 256;      // 0..1023 float4 slots
            int t = idx >> 4, c4 = idx & 15;
            *reinterpret_cast<float4*>(&Vs[t][c4 * 4]) =
                *reinterpret_cast<const float4*>(&Vg[(j0 + t) * DKK + c4 * 4]);
        }
        __syncthreads();

        // scores tile = Q . K^T
        float sc[4][4] = {};
        #pragma unroll 16
        for (int kk = 0; kk < 64; kk++) {
            float a[4], b[4];
            #pragma unroll
            for (int i = 0; i < 4; i++) a[i] = Qs[kk][ty * 4 + i];
            #pragma unroll
            for (int jj = 0; jj < 4; jj++) b[jj] = Ks[kk][tx * 4 + jj];
            #pragma unroll
            for (int i = 0; i < 4; i++)
                #pragma unroll
                for (int jj = 0; jj < 4; jj++)
                    sc[i][jj] += a[i] * b[jj];
        }

        const bool diag = (j == qi);
        float rmax[4];
        #pragma unroll
        for (int i = 0; i < 4; i++) {
            rmax[i] = -1e30f;
            #pragma unroll
            for (int jj = 0; jj < 4; jj++) {
                float s_ = sc[i][jj] * scale;
                if (diag && (j0 + tx * 4 + jj) > (i0 + ty * 4 + i)) s_ = -1e30f;
                sc[i][jj] = s_;
                rmax[i] = fmaxf(rmax[i], s_);
            }
        }
        #pragma unroll
        for (int off = 8; off > 0; off >>= 1)
            #pragma unroll
            for (int i = 0; i < 4; i++)
                rmax[i] = fmaxf(rmax[i], __shfl_xor_sync(0xffffffffu, rmax[i], off));

        #pragma unroll
        for (int i = 0; i < 4; i++) {
            float mnew = fmaxf(mrow[i], rmax[i]);
            float corr = __expf(mrow[i] - mnew);
            mrow[i] = mnew;
            float rs = 0.f;
            #pragma unroll
            for (int jj = 0; jj < 4; jj++) {
                float p = __expf(sc[i][jj] - mnew);
                sc[i][jj] = p;
                rs += p;
            }
            #pragma unroll
            for (int off = 8; off > 0; off >>= 1)
                rs += __shfl_xor_sync(0xffffffffu, rs, off);
            lsum[i] = lsum[i] * corr + rs;
            #pragma unroll
            for (int c = 0; c < 4; c++) acc[i][c] *= corr;
        }

        // write P transposed: Ps[t][r]
        #pragma unroll
        for (int i = 0; i < 4; i++)
            #pragma unroll
            for (int jj = 0; jj < 4; jj++)
                Ps[tx * 4 + jj][ty * 4 + i] = sc[i][jj];
        __syncthreads();

        // acc += P @ V
        #pragma unroll 16
        for (int kk = 0; kk < 64; kk++) {
            float a[4], b[4];
            #pragma unroll
            for (int i = 0; i < 4; i++) a[i] = Ps[kk][ty * 4 + i];
            #pragma unroll
            for (int jj = 0; jj < 4; jj++) b[jj] = Vs[kk][tx * 4 + jj];
            #pragma unroll
            for (int i = 0; i < 4; i++)
                #pragma unroll
                for (int jj = 0; jj < 4; jj++)
                    acc[i][jj] += a[i] * b[jj];
        }
    }

    // epilogue: divide by l, write to [b, s, h*64 + c]
    const int b_ = bh / HH, h = bh % HH;
    #pragma unroll
    for (int i = 0; i < 4; i++) {
        float inv = 1.f / lsum[i];
        int s = i0 + ty * 4 + i;
        float* orow = &g_Ctx[((size_t)(b_ * SS + s)) * DD + h * DKK];
        float4 o4 = make_float4(acc[i][0] * inv, acc[i][1] * inv,
                                acc[i][2] * inv, acc[i][3] * inv);
        *reinterpret_cast<float4*>(orow + tx * 4) = o4;
    }
}

// ---------------------------------------------------------------------------
// Kernel 3: output projection. out[m][n] = sum_c Ctx[m][c] * Wo[n][c] + bo[n]
// grid: (M/64, D/64), block 256.
// ---------------------------------------------------------------------------
__global__ __launch_bounds__(256) void outproj_kernel(
    const float* __restrict__ Wo, const float* __restrict__ bo, float* __restrict__ out)
{
    __shared__ float As[16][65];   // As[kk][m]
    __shared__ float Bs[16][65];   // Bs[kk][n] = Wo[n][c]
    const int m0 = blockIdx.x * 64;
    const int n0 = blockIdx.y * 64;
    const int tid = threadIdx.x;
    const int tx = tid & 15, ty = tid >> 4;
    const int lr = tid >> 2, lq = tid & 3;

    float acc[4][4] = {};

    for (int c0 = 0; c0 < DD; c0 += 16) {
        float4 a4 = *reinterpret_cast<const float4*>(&g_Ctx[(size_t)(m0 + lr) * DD + c0 + lq * 4]);
        As[lq*4+0][lr] = a4.x; As[lq*4+1][lr] = a4.y;
        As[lq*4+2][lr] = a4.z; As[lq*4+3][lr] = a4.w;
        float4 b4 = *reinterpret_cast<const float4*>(&Wo[(size_t)(n0 + lr) * DD + c0 + lq * 4]);
        Bs[lq*4+0][lr] = b4.x; Bs[lq*4+1][lr] = b4.y;
        Bs[lq*4+2][lr] = b4.z; Bs[lq*4+3][lr] = b4.w;
        __syncthreads();
        #pragma unroll
        for (int kk = 0; kk < 16; kk++) {
            float a[4], b[4];
            #pragma unroll
            for (int i = 0; i < 4; i++) a[i] = As[kk][ty * 4 + i];
            #pragma unroll
            for (int j = 0; j < 4; j++) b[j] = Bs[kk][tx * 4 + j];
            #pragma unroll
            for (int i = 0; i < 4; i++)
                #pragma unroll
                for (int j = 0; j < 4; j++)
                    acc[i][j] += a[i] * b[j];
        }
        __syncthreads();
    }

    #pragma unroll
    for (int i = 0; i < 4; i++) {
        int m = m0 + ty * 4 + i;
        float4 bb = *reinterpret_cast<const float4*>(&bo[n0 + tx * 4]);
        float4 o4 = make_float4(acc[i][0] + bb.x, acc[i][1] + bb.y,
                                acc[i][2] + bb.z, acc[i][3] + bb.w);
        *reinterpret_cast<float4*>(&out[(size_t)m * DD + n0 + tx * 4]) = o4;
    }
}

// ---------------------------------------------------------------------------
extern "C" void kernel_launch(void* const* d_in, const int* in_sizes, int n_in,
                              void* d_out, int out_size)
{
    const float* q  = (const float*)d_in[0];
    const float* k  = (const float*)d_in[1];
    const float* v  = (const float*)d_in[2];
    const float* Wq = (const float*)d_in[3];
    const float* Wk = (const float*)d_in[4];
    const float* Wv = (const float*)d_in[5];
    const float* Wo = (const float*)d_in[6];
    const float* bo = (const float*)d_in[7];
    float* out = (float*)d_out;

    proj_kernel<<<dim3(MM / 64, HH, 3), 256>>>(q, k, v, Wq, Wk, Wv);

    int smem_bytes = (3 * 64 * 65 + 64 * 64) * (int)sizeof(float);   // ~66 KB
    cudaFuncSetAttribute(attn_kernel, cudaFuncAttributeMaxDynamicSharedMemorySize, smem_bytes);
    attn_kernel<<<dim3(SS / 64, BHH), 256, smem_bytes>>>();

    outproj_kernel<<<dim3(MM / 64, DD / 64), 256>>>(Wo, bo, out);
}